// round 6
// baseline (speedup 1.0000x reference)
#include <cuda_runtime.h>
#include <cuda_bf16.h>
#include <cstdint>

#define BATCH 4096
#define NHID  512
#define BR    32
#define NBKT  1024   // bucket key = lab>>5 ; node2 = 33+bkt, node1 = 1+(bkt>>5)

#define L0_BLOCKS 512          // 4096/8 groups, S=8
#define L1_SLOTS  544          // >= 32 + 4096/8 worst-case level-1 groups (S=8)
#define L2_SLOTS  2048         // >= 1024 + 4096/4 worst-case level-2 groups (S=4)

__device__ int   d_start[NBKT + 1];
__device__ int   d_cur[NBKT];
__device__ int   d_perm[BATCH];
__device__ int   d_g1off[33];        // prefix of level-1 group counts per node
__device__ int   d_g2off[NBKT + 1];  // prefix of level-2 group counts per bucket
__device__ float d_p[3][BATCH];      // per-level probabilities

// ---------------- f32x2 helpers (packed FMA is PTX-only on sm_103a) ----------------
__device__ __forceinline__ void fma2(uint64_t& d, uint64_t a, uint64_t b) {
    asm("fma.rn.f32x2 %0, %1, %2, %0;" : "+l"(d) : "l"(a), "l"(b));
}
__device__ __forceinline__ uint64_t pack2(float v) {
    uint64_t r; asm("mov.b64 %0, {%1, %1};" : "=l"(r) : "f"(v)); return r;
}
__device__ __forceinline__ void unpack2(float& lo, float& hi, uint64_t v) {
    asm("mov.b64 {%0, %1}, %2;" : "=f"(lo), "=f"(hi) : "l"(v));
}
__device__ __forceinline__ void lds_v2u64(uint64_t& a, uint64_t& b, uint32_t addr) {
    asm volatile("ld.shared.v2.u64 {%0, %1}, [%2];" : "=l"(a), "=l"(b) : "r"(addr));
}
__device__ __forceinline__ uint32_t smem_u32(const void* p) {
    return (uint32_t)__cvta_generic_to_shared(p);
}

// ---------------- tables kernel: hist + scans + task tables (NO scatter) ----------------
__global__ __launch_bounds__(1024, 1)
void tables_kernel(const int* __restrict__ labels)
{
    __shared__ int hist[NBKT];
    __shared__ int wsum[32];
    __shared__ int l1cnt[32];

    const int t    = threadIdx.x;
    const int wid  = t >> 5;
    const int lane = t & 31;

    hist[t] = 0;
    __syncthreads();
    #pragma unroll
    for (int i = 0; i < 4; i++)
        atomicAdd(&hist[labels[t + i * 1024] >> 5], 1);
    __syncthreads();

    // exclusive scan of hist
    const int h = hist[t];
    int v = h;
    #pragma unroll
    for (int o = 1; o < 32; o <<= 1) {
        int u = __shfl_up_sync(0xffffffffu, v, o);
        if (lane >= o) v += u;
    }
    if (lane == 31) wsum[wid] = v;
    __syncthreads();
    if (wid == 0) {
        int w = wsum[lane];
        #pragma unroll
        for (int o = 1; o < 32; o <<= 1) {
            int u = __shfl_up_sync(0xffffffffu, w, o);
            if (lane >= o) w += u;
        }
        wsum[lane] = w;
    }
    __syncthreads();
    const int excl = v + (wid > 0 ? wsum[wid - 1] : 0) - h;
    d_start[t] = excl;
    d_cur[t]   = excl;
    if (t == 0) d_start[NBKT] = BATCH;
    __syncthreads();

    // level-2 group prefix: ceil(n_bkt/4)
    int g2 = (h + 3) >> 2;
    int v2 = g2;
    #pragma unroll
    for (int o = 1; o < 32; o <<= 1) {
        int u = __shfl_up_sync(0xffffffffu, v2, o);
        if (lane >= o) v2 += u;
    }
    if (lane == 31) wsum[wid] = v2;
    __syncthreads();
    if (wid == 0) {
        int w = wsum[lane];
        #pragma unroll
        for (int o = 1; o < 32; o <<= 1) {
            int u = __shfl_up_sync(0xffffffffu, w, o);
            if (lane >= o) w += u;
        }
        wsum[lane] = w;
    }
    __syncthreads();
    const int incl2 = v2 + (wid > 0 ? wsum[wid - 1] : 0);
    d_g2off[t] = incl2 - g2;
    if (t == 1023) d_g2off[NBKT] = incl2;

    // level-1 group prefix: node w owns buckets [32w, 32w+32)
    {
        int c = hist[wid * 32 + lane];
        #pragma unroll
        for (int o = 16; o; o >>= 1) c += __shfl_xor_sync(0xffffffffu, c, o);
        if (lane == 0) l1cnt[wid] = (c + 7) >> 3;
    }
    __syncthreads();
    if (t == 0) {
        int acc = 0;
        d_g1off[0] = 0;
        #pragma unroll
        for (int g = 0; g < 32; g++) { acc += l1cnt[g]; d_g1off[g + 1] = acc; }
    }
}

// ---------------- scatter kernel: 16 blocks spread the scattered STGs ----------------
__global__ __launch_bounds__(256)
void scatter_kernel(const int* __restrict__ labels)
{
    const int i = blockIdx.x * 256 + threadIdx.x;
    const int p = atomicAdd(&d_cur[labels[i] >> 5], 1);
    d_perm[p] = i;
}

// largest k with off[k] <= i
__device__ __forceinline__ int find_bucket(const int* __restrict__ off, int n, int i)
{
    int lo = 0, hi = n;
    while (lo + 1 < hi) {
        int mid = (lo + hi) >> 1;
        if (off[mid] <= i) lo = mid; else hi = mid;
    }
    return lo;
}

// ---------------- group task: SMAX samples x one node, 4-warp h-split, f32x2 FMA ------
// x staged TRANSPOSED: xst[h][s] so ld.shared.v2.u64 yields 4 samples' x[h];
// W value broadcast-packed (w,w); samples paired in packed accumulators.
template<int SMAX, int LOG2S>
__device__ __forceinline__ void process_group(
    const float* __restrict__ x, const int* __restrict__ labels,
    const float* __restrict__ W, float* __restrict__ pout,
    float* __restrict__ xst,         // [512][SMAX] transposed staging
    float* __restrict__ part,        // [4][SMAX][32]
    int* __restrict__ sid_sm, int* __restrict__ step_sm,
    int node, int shift, int base, int S, bool use_perm)
{
    const int tid  = threadIdx.x;
    const int warp = tid >> 5;
    const int lane = tid & 31;

    if (tid < S) {
        const int sb = use_perm ? d_perm[base + tid] : (base + tid);
        sid_sm[tid]  = sb;
        step_sm[tid] = (labels[sb] >> shift) & 31;
    }
    __syncthreads();

    // Stage transposed: thread = (s = tid & (SMAX-1), hq over iterations)
    {
        const int s = tid & (SMAX - 1);
        const bool ok = (s < S);
        const float4* xg = ok
            ? reinterpret_cast<const float4*>(x + (size_t)sid_sm[s] * NHID) : nullptr;
        #pragma unroll
        for (int it = 0; it < SMAX; it++) {
            const int hq = (tid >> LOG2S) + it * (128 >> LOG2S);
            float4 v = ok ? __ldg(xg + hq) : make_float4(0.f, 0.f, 0.f, 0.f);
            xst[(4 * hq + 0) * SMAX + s] = v.x;
            xst[(4 * hq + 1) * SMAX + s] = v.y;
            xst[(4 * hq + 2) * SMAX + s] = v.z;
            xst[(4 * hq + 3) * SMAX + s] = v.w;
        }
    }
    __syncthreads();

    const float* __restrict__ Wq =
        W + (size_t)node * (NHID * BR) + (warp * 128) * BR + lane;
    const uint32_t xbase = smem_u32(xst) + (warp * 128) * SMAX * 4;

    uint64_t acc2[SMAX / 2];
    #pragma unroll
    for (int p = 0; p < SMAX / 2; p++) acc2[p] = 0ull;

    #pragma unroll 4
    for (int t = 0; t < 32; t++) {
        const float w0 = __ldg(Wq + (4 * t + 0) * BR);
        const float w1 = __ldg(Wq + (4 * t + 1) * BR);
        const float w2 = __ldg(Wq + (4 * t + 2) * BR);
        const float w3 = __ldg(Wq + (4 * t + 3) * BR);
        const float wv[4] = {w0, w1, w2, w3};
        #pragma unroll
        for (int j = 0; j < 4; j++) {
            const uint64_t wp = pack2(wv[j]);
            const uint32_t a  = xbase + (4 * t + j) * SMAX * 4;
            if (SMAX == 8) {
                uint64_t p0, p1, p2, p3;
                lds_v2u64(p0, p1, a);
                lds_v2u64(p2, p3, a + 16);
                fma2(acc2[0], p0, wp);
                fma2(acc2[1], p1, wp);
                fma2(acc2[2], p2, wp);
                fma2(acc2[3], p3, wp);
            } else {
                uint64_t p0, p1;
                lds_v2u64(p0, p1, a);
                fma2(acc2[0], p0, wp);
                fma2(acc2[1], p1, wp);
            }
        }
    }

    #pragma unroll
    for (int p = 0; p < SMAX / 2; p++) {
        float lo, hi;
        unpack2(lo, hi, acc2[p]);
        part[(warp * SMAX + 2 * p + 0) * 32 + lane] = lo;
        part[(warp * SMAX + 2 * p + 1) * 32 + lane] = hi;
    }
    __syncthreads();

    #pragma unroll
    for (int si = warp; si < SMAX; si += 4) {
        float logit = part[(0 * SMAX + si) * 32 + lane]
                    + part[(1 * SMAX + si) * 32 + lane]
                    + part[(2 * SMAX + si) * 32 + lane]
                    + part[(3 * SMAX + si) * 32 + lane];
        float m = logit;
        #pragma unroll
        for (int o = 16; o; o >>= 1) m = fmaxf(m, __shfl_xor_sync(0xffffffffu, m, o));
        const float e = __expf(logit - m);
        float ssum = e;
        #pragma unroll
        for (int o = 16; o; o >>= 1) ssum += __shfl_xor_sync(0xffffffffu, ssum, o);
        if (si < S) {
            const float es = __shfl_sync(0xffffffffu, e, step_sm[si]);
            if (lane == 0) pout[sid_sm[si]] = es / ssum;
        }
    }
}

// ---------------- unified levels kernel: exactly ONE group per block ----------------
__global__ __launch_bounds__(128)
void levels_kernel(const float* __restrict__ x,
                   const int* __restrict__ labels,
                   const float* __restrict__ W)
{
    __shared__ float xst[512 * 8];         // 16 KB (SMAX=4 path uses first 8 KB)
    __shared__ float part[4 * 8 * 32];     // 4 KB
    __shared__ int   sid_sm[8];
    __shared__ int   step_sm[8];

    const int blk = blockIdx.x;

    if (blk < L0_BLOCKS) {
        process_group<8, 3>(x, labels, W, d_p[0], xst, part, sid_sm, step_sm,
                            /*node=*/0, /*shift=*/10, blk * 8, 8, false);
    } else if (blk < L0_BLOCKS + L1_SLOTS) {
        const int i = blk - L0_BLOCKS;
        if (i >= d_g1off[32]) return;
        const int g    = find_bucket(d_g1off, 32, i);
        const int base = d_start[g * 32] + (i - d_g1off[g]) * 8;
        const int S    = min(8, d_start[g * 32 + 32] - base);
        process_group<8, 3>(x, labels, W, d_p[1], xst, part, sid_sm, step_sm,
                            1 + g, /*shift=*/5, base, S, true);
    } else {
        const int i = blk - (L0_BLOCKS + L1_SLOTS);
        if (i >= d_g2off[NBKT]) return;
        const int k    = find_bucket(d_g2off, NBKT, i);
        const int base = d_start[k] + (i - d_g2off[k]) * 4;
        const int S    = min(4, d_start[k + 1] - base);
        process_group<4, 2>(x, labels, W, d_p[2], xst, part, sid_sm, step_sm,
                            33 + k, /*shift=*/0, base, S, true);
    }
}

__global__ __launch_bounds__(256)
void combine_kernel(float* __restrict__ out)
{
    const int b = blockIdx.x * 256 + threadIdx.x;
    out[b] = d_p[0][b] * d_p[1][b] * d_p[2][b];
}

extern "C" void kernel_launch(void* const* d_in, const int* in_sizes, int n_in,
                              void* d_out, int out_size)
{
    const float* x      = (const float*)d_in[0];   // [4096, 512] f32
    const int*   labels = (const int*)d_in[1];     // [4096] i32
    const float* W      = (const float*)d_in[2];   // [1057, 512, 32] f32
    float*       out    = (float*)d_out;           // [4096] f32

    tables_kernel <<<1, 1024>>>(labels);
    scatter_kernel<<<16, 256>>>(labels);
    levels_kernel <<<L0_BLOCKS + L1_SLOTS + L2_SLOTS, 128>>>(x, labels, W);
    combine_kernel<<<BATCH / 256, 256>>>(out);
}